// round 14
// baseline (speedup 1.0000x reference)
#include <cuda_runtime.h>
#include <cuda_fp16.h>
#include <cstdint>

#define N_NODES 50000
#define E_EDGES 1600000
#define E_TOT   (E_EDGES + N_NODES)   // with self loops
#define C1      128                    // HEADS*HID
#define HEADS   8
#define HID     16
#define NEG_SLOPE 0.2f
#define CAP     192                    // max in-degree bucket (Poisson(33) graph)

// ---------------- scratch (device globals; no allocation allowed) ----------
// RULE: never pass these as kernel arguments from host code (host-shadow +
// GB300 ATS silently lands writes in host memory). Reference directly.
__device__ __align__(16) __half g_h1h[N_NODES * C1];   // x @ W1, fp16 (gather-only)
__device__ __align__(16) float g_as1[N_NODES * HEADS];
__device__ __align__(16) float g_ad1[N_NODES * HEADS];
__device__ __align__(16) float g_z[N_NODES];           // layer-2 linear output
__device__ int   g_count[N_NODES];                     // in-degree (incl self loop)
__device__ int   g_srcs[N_NODES * CAP];                // CSR-ish buckets by dst
__device__ int   g_is64;                               // edge_index dtype flag

// ------------- helpers -----------------------------------------------------
__device__ __forceinline__ float lrelu(float v) {
    return v > 0.f ? v : NEG_SLOPE * v;
}
__device__ __forceinline__ void load_edge(const void* ei, int e, int& s, int& d) {
    if (e >= E_EDGES) { s = d = e - E_EDGES; return; }  // self loop
    if (g_is64) {
        const long long* p = (const long long*)ei;
        s = (int)p[e]; d = (int)p[E_EDGES + e];
    } else {
        const int* p = (const int*)ei;
        s = p[e]; d = p[E_EDGES + e];
    }
}

// ------------- detect edge_index dtype -------------------------------------
__global__ void detect_kernel(const void* ei) {
    const long long* p = (const long long*)ei;
    int ok = 1;
    for (int i = 0; i < 256; i++) {
        long long v = p[i];
        if (v < 0 || v >= N_NODES) { ok = 0; break; }
    }
    g_is64 = ok;
}

// ------------- zero degree counters ----------------------------------------
__global__ void zero_kernel() {
    int i = blockIdx.x * blockDim.x + threadIdx.x;
    if (i < N_NODES) g_count[i] = 0;
}

// ------------- scatter edges into dst buckets ------------------------------
__global__ void scatter_kernel(const void* __restrict__ ei) {
    int e = blockIdx.x * blockDim.x + threadIdx.x;
    if (e >= E_TOT) return;
    int s, d; load_edge(ei, e, s, d);
    int pos = atomicAdd(&g_count[d], 1);
    if (pos < CAP) g_srcs[d * CAP + pos] = s;
}

// ------------- GEMM1 + fused attention coefficients ------------------------
// h1 = x @ W1 (N x 128 @ 128 x 128), packed fp32x2 FFMA (row-pair accum).
// B is stored pre-duplicated {w,w} in smem with swizzled column layout
// (col c -> slot (c&3)*32 + (c>>2)) so the hot loop has no packing movs and
// conflict-free LDS.64. Epilogue: h1 -> fp16; as1/ad1 segmented reduction.
#define GT_M 64
#define GT_K 32
__global__ void __launch_bounds__(256) gemm1_kernel(
        const float* __restrict__ x,
        const float* __restrict__ W,
        const float* __restrict__ att_s,
        const float* __restrict__ att_d) {
    // GT_M+2 pad: keeps &As[kk][even] 8B-aligned for LDS.64 row-pair loads
    __shared__ __align__(16) float  As[GT_K][GT_M + 2];
    __shared__ __align__(16) float2 Bs2[GT_K][C1];
    int row0 = blockIdx.x * GT_M;
    int t = threadIdx.x;                  // 256 threads
    int r0 = (t >> 5) * 8;                // 8 rows / warp (whole warp same rows)
    int lane = t & 31;
    int c0 = lane * 4;                    // 4 cols / thread

    // acc2[p][j] = {acc[row 2p][col c0+j], acc[row 2p+1][col c0+j]} f32x2
    uint64_t acc2[4][4];
#pragma unroll
    for (int p = 0; p < 4; p++)
#pragma unroll
        for (int j = 0; j < 4; j++) acc2[p][j] = 0ull;

    for (int k0 = 0; k0 < C1; k0 += GT_K) {
#pragma unroll
        for (int i = 0; i < 8; i++) {          // A tile 64x32
            int idx = t + i * 256;
            int r = idx >> 5, kk = idx & 31;
            int gr = row0 + r;
            As[kk][r] = (gr < N_NODES) ? x[gr * C1 + k0 + kk] : 0.f;
        }
#pragma unroll
        for (int i = 0; i < 16; i++) {         // B tile 32x128, duplicated
            int idx = t + i * 256;
            int kk = idx >> 7, c = idx & 127;
            float w = W[(k0 + kk) * C1 + c];
            Bs2[kk][(c & 3) * 32 + (c >> 2)] = make_float2(w, w);
        }
        __syncthreads();
#pragma unroll
        for (int kk = 0; kk < GT_K; kk++) {
            uint64_t ap[4];
#pragma unroll
            for (int p = 0; p < 4; p++)
                ap[p] = *(const uint64_t*)&As[kk][r0 + 2 * p];
            uint64_t bb[4];
#pragma unroll
            for (int j = 0; j < 4; j++)
                bb[j] = *(const uint64_t*)&Bs2[kk][j * 32 + lane];
#pragma unroll
            for (int p = 0; p < 4; p++)
#pragma unroll
                for (int j = 0; j < 4; j++)
                    asm("fma.rn.f32x2 %0, %1, %2, %3;"
                        : "=l"(acc2[p][j])
                        : "l"(ap[p]), "l"(bb[j]), "l"(acc2[p][j]));
        }
        __syncthreads();
    }

    // unpack accumulators: acc[i][j], rows i = 0..7 (global row row0+r0+i)
    float acc[8][4];
#pragma unroll
    for (int p = 0; p < 4; p++)
#pragma unroll
        for (int j = 0; j < 4; j++) {
            float lo, hi;
            asm("mov.b64 {%0, %1}, %2;" : "=f"(lo), "=f"(hi) : "l"(acc2[p][j]));
            acc[2 * p][j] = lo;
            acc[2 * p + 1][j] = hi;
        }

    // att vectors for this lane's 4 columns (head = lane>>2, same for all 4)
    float4 as4 = *(const float4*)(att_s + c0);
    float4 ad4 = *(const float4*)(att_d + c0);
    int h = lane >> 2;

#pragma unroll
    for (int i = 0; i < 8; i++) {
        int gr = row0 + r0 + i;
        if (gr < N_NODES) {
            __half2 p0 = __floats2half2_rn(acc[i][0], acc[i][1]);
            __half2 p1 = __floats2half2_rn(acc[i][2], acc[i][3]);
            uint2 pk = make_uint2(*(uint32_t*)&p0, *(uint32_t*)&p1);
            *(uint2*)(g_h1h + (long long)gr * C1 + c0) = pk;
        }
        float ps = acc[i][0] * as4.x + acc[i][1] * as4.y
                 + acc[i][2] * as4.z + acc[i][3] * as4.w;
        float pd = acc[i][0] * ad4.x + acc[i][1] * ad4.y
                 + acc[i][2] * ad4.z + acc[i][3] * ad4.w;
        ps += __shfl_xor_sync(0xffffffffu, ps, 1);
        ps += __shfl_xor_sync(0xffffffffu, ps, 2);
        pd += __shfl_xor_sync(0xffffffffu, pd, 1);
        pd += __shfl_xor_sync(0xffffffffu, pd, 2);
        if ((lane & 3) == 0 && gr < N_NODES) {
            g_as1[gr * HEADS + h] = ps;
            g_ad1[gr * HEADS + h] = pd;
        }
    }
}

// ------------- layer-1 aggregation, fused through z (warp per dst node) ----
__global__ void agg1_kernel(const float* __restrict__ b1,
                            const float* __restrict__ W2) {
    int n = blockIdx.x * (blockDim.x >> 5) + (threadIdx.x >> 5);
    if (n >= N_NODES) return;
    int lane = threadIdx.x & 31;
    int h = lane >> 2;                     // head of this lane
    int cnt = g_count[n]; if (cnt > CAP) cnt = CAP;
    float ad = g_ad1[n * HEADS + h];

    float4 acc = make_float4(0.f, 0.f, 0.f, 0.f);
    float wsum = 0.f;
    const int* bucket = g_srcs + n * CAP;

    int i = 0;
    for (; i + 4 <= cnt; i += 4) {
        int s0 = bucket[i], s1 = bucket[i + 1];
        int s2 = bucket[i + 2], s3 = bucket[i + 3];
        float e0 = g_as1[s0 * HEADS + h];
        float e1 = g_as1[s1 * HEADS + h];
        float e2 = g_as1[s2 * HEADS + h];
        float e3 = g_as1[s3 * HEADS + h];
        uint2 r0 = *(const uint2*)(g_h1h + (long long)s0 * C1 + lane * 4);
        uint2 r1 = *(const uint2*)(g_h1h + (long long)s1 * C1 + lane * 4);
        uint2 r2 = *(const uint2*)(g_h1h + (long long)s2 * C1 + lane * 4);
        uint2 r3 = *(const uint2*)(g_h1h + (long long)s3 * C1 + lane * 4);
        float w0 = __expf(lrelu(e0 + ad));
        float w1 = __expf(lrelu(e1 + ad));
        float w2 = __expf(lrelu(e2 + ad));
        float w3 = __expf(lrelu(e3 + ad));
        wsum += (w0 + w1) + (w2 + w3);
        float2 a0 = __half22float2(*(__half2*)&r0.x);
        float2 a1 = __half22float2(*(__half2*)&r0.y);
        float2 b0 = __half22float2(*(__half2*)&r1.x);
        float2 b1v = __half22float2(*(__half2*)&r1.y);
        float2 c0v = __half22float2(*(__half2*)&r2.x);
        float2 c1v = __half22float2(*(__half2*)&r2.y);
        float2 d0 = __half22float2(*(__half2*)&r3.x);
        float2 d1 = __half22float2(*(__half2*)&r3.y);
        acc.x += (w0 * a0.x + w1 * b0.x) + (w2 * c0v.x + w3 * d0.x);
        acc.y += (w0 * a0.y + w1 * b0.y) + (w2 * c0v.y + w3 * d0.y);
        acc.z += (w0 * a1.x + w1 * b1v.x) + (w2 * c1v.x + w3 * d1.x);
        acc.w += (w0 * a1.y + w1 * b1v.y) + (w2 * c1v.y + w3 * d1.y);
    }
    for (; i < cnt; i++) {
        int s0 = bucket[i];
        float e0 = g_as1[s0 * HEADS + h];
        uint2 r0 = *(const uint2*)(g_h1h + (long long)s0 * C1 + lane * 4);
        float2 a0 = __half22float2(*(__half2*)&r0.x);
        float2 a1 = __half22float2(*(__half2*)&r0.y);
        float w0 = __expf(lrelu(e0 + ad));
        wsum += w0;
        acc.x += w0 * a0.x; acc.y += w0 * a0.y;
        acc.z += w0 * a1.x; acc.w += w0 * a1.y;
    }

    float inv = 1.f / (wsum + 1e-16f);
    float4 b = *(const float4*)(b1 + lane * 4);
    float4 w = *(const float4*)(W2 + lane * 4);
    float x0 = acc.x * inv + b.x, x1 = acc.y * inv + b.y;
    float x2 = acc.z * inv + b.z, x3 = acc.w * inv + b.w;
    x0 = x0 > 0.f ? x0 : (__expf(x0) - 1.f);
    x1 = x1 > 0.f ? x1 : (__expf(x1) - 1.f);
    x2 = x2 > 0.f ? x2 : (__expf(x2) - 1.f);
    x3 = x3 > 0.f ? x3 : (__expf(x3) - 1.f);
    float p = x0 * w.x + x1 * w.y + x2 * w.z + x3 * w.w;
#pragma unroll
    for (int o = 16; o; o >>= 1) p += __shfl_xor_sync(0xffffffffu, p, o);
    if (lane == 0) g_z[n] = p;
}

// ------------- layer-2 aggregation (warp per dst node) ---------------------
__global__ void agg2_kernel(const float* __restrict__ att_s,
                            const float* __restrict__ att_d,
                            const float* __restrict__ b2,
                            float* __restrict__ out) {
    int n = blockIdx.x * (blockDim.x >> 5) + (threadIdx.x >> 5);
    if (n >= N_NODES) return;
    int lane = threadIdx.x & 31;
    int cnt = g_count[n]; if (cnt > CAP) cnt = CAP;
    float zd_ad = g_z[n] * att_d[0];
    float a_s = att_s[0];
    const int* bucket = g_srcs + n * CAP;

    float num = 0.f, den = 0.f;
    for (int i = lane; i < cnt; i += 32) {
        int s = bucket[i];
        float zs = g_z[s];
        float w = __expf(lrelu(zs * a_s + zd_ad));
        num += zs * w;
        den += w;
    }
#pragma unroll
    for (int o = 16; o; o >>= 1) {
        num += __shfl_xor_sync(0xffffffffu, num, o);
        den += __shfl_xor_sync(0xffffffffu, den, o);
    }
    if (lane == 0) out[n] = num / (den + 1e-16f) + b2[0];
}

// ------------- launch ------------------------------------------------------
extern "C" void kernel_launch(void* const* d_in, const int* in_sizes, int n_in,
                              void* d_out, int out_size) {
    const float* x        = (const float*)d_in[0];
    const void*  ei       = d_in[1];               // int64 or int32 (detected)
    const float* W1       = (const float*)d_in[2];
    const float* att_src1 = (const float*)d_in[3];
    const float* att_dst1 = (const float*)d_in[4];
    const float* b1       = (const float*)d_in[5];
    const float* W2       = (const float*)d_in[6];
    const float* att_src2 = (const float*)d_in[7];
    const float* att_dst2 = (const float*)d_in[8];
    const float* b2       = (const float*)d_in[9];
    float* out = (float*)d_out;

    // side stream + events (created once on first, uncaptured, call;
    // streams/events are not device-memory allocations)
    static cudaStream_t s_side = nullptr;
    static cudaEvent_t ev_fork = nullptr, ev_join = nullptr;
    if (!s_side) {
        cudaStreamCreateWithFlags(&s_side, cudaStreamNonBlocking);
        cudaEventCreateWithFlags(&ev_fork, cudaEventDisableTiming);
        cudaEventCreateWithFlags(&ev_join, cudaEventDisableTiming);
    }

    detect_kernel<<<1, 1>>>(ei);

    // fork: zero+scatter on side stream, gemm1 on main stream (disjoint data)
    cudaEventRecord(ev_fork, 0);
    cudaStreamWaitEvent(s_side, ev_fork, 0);

    zero_kernel<<<(N_NODES + 255) / 256, 256, 0, s_side>>>();
    scatter_kernel<<<(E_TOT + 255) / 256, 256, 0, s_side>>>(ei);

    gemm1_kernel<<<(N_NODES + GT_M - 1) / GT_M, 256>>>(x, W1, att_src1, att_dst1);

    // join
    cudaEventRecord(ev_join, s_side);
    cudaStreamWaitEvent(0, ev_join, 0);

    agg1_kernel<<<(N_NODES * 32 + 255) / 256, 256>>>(b1, W2);

    agg2_kernel<<<(N_NODES * 32 + 255) / 256, 256>>>(att_src2, att_dst2, b2, out);
}

// round 15
// speedup vs baseline: 1.1687x; 1.1687x over previous
#include <cuda_runtime.h>
#include <cuda_fp16.h>
#include <cstdint>

#define N_NODES 50000
#define E_EDGES 1600000
#define E_TOT   (E_EDGES + N_NODES)   // with self loops
#define C1      128                    // HEADS*HID
#define HEADS   8
#define HID     16
#define NEG_SLOPE 0.2f
#define CAP     192                    // max in-degree bucket (Poisson(33) graph)

// ---------------- scratch (device globals; no allocation allowed) ----------
// RULE: never pass these as kernel arguments from host code (host-shadow +
// GB300 ATS silently lands writes in host memory). Reference directly.
__device__ __align__(16) __half g_h1h[N_NODES * C1];   // x @ W1, fp16 (gather-only)
__device__ __align__(16) float g_as1[N_NODES * HEADS];
__device__ __align__(16) float g_ad1[N_NODES * HEADS];
__device__ __align__(16) float g_z[N_NODES];           // layer-2 linear output
__device__ int   g_count[N_NODES];                     // in-degree (incl self loop)
__device__ int   g_srcs[N_NODES * CAP];                // CSR-ish buckets by dst
__device__ int   g_is64;                               // edge_index dtype flag

// ------------- helpers -----------------------------------------------------
__device__ __forceinline__ float lrelu(float v) {
    return v > 0.f ? v : NEG_SLOPE * v;
}
__device__ __forceinline__ void load_edge(const void* ei, int e, int& s, int& d) {
    if (e >= E_EDGES) { s = d = e - E_EDGES; return; }  // self loop
    if (g_is64) {
        const long long* p = (const long long*)ei;
        s = (int)p[e]; d = (int)p[E_EDGES + e];
    } else {
        const int* p = (const int*)ei;
        s = p[e]; d = p[E_EDGES + e];
    }
}

// ------------- detect edge_index dtype -------------------------------------
__global__ void detect_kernel(const void* ei) {
    const long long* p = (const long long*)ei;
    int ok = 1;
    for (int i = 0; i < 256; i++) {
        long long v = p[i];
        if (v < 0 || v >= N_NODES) { ok = 0; break; }
    }
    g_is64 = ok;
}

// ------------- zero degree counters ----------------------------------------
__global__ void zero_kernel() {
    int i = blockIdx.x * blockDim.x + threadIdx.x;
    if (i < N_NODES) g_count[i] = 0;
}

// ------------- scatter edges into dst buckets ------------------------------
__global__ void scatter_kernel(const void* __restrict__ ei) {
    int e = blockIdx.x * blockDim.x + threadIdx.x;
    if (e >= E_TOT) return;
    int s, d; load_edge(ei, e, s, d);
    int pos = atomicAdd(&g_count[d], 1);
    if (pos < CAP) g_srcs[d * CAP + pos] = s;
}

// ------------- GEMM1 + fused attention coefficients ------------------------
// h1 = x @ W1 (N x 128 @ 128 x 128), packed fp32x2 FFMA.
// M-tile 128: each thread computes 16 rows x 4 cols (8 f32x2 accum per col).
// B kept plain in smem; broadcast-pack via mov.b64 (R13-proven layout).
// Epilogue: h1 -> fp16; as1/ad1 segmented warp reduction.
#define GT_M 128
#define GT_K 32
__global__ void __launch_bounds__(256) gemm1_kernel(
        const float* __restrict__ x,
        const float* __restrict__ W,
        const float* __restrict__ att_s,
        const float* __restrict__ att_d) {
    // +2 pad keeps &As[kk][even] 8B-aligned for LDS.64 row-pair loads
    __shared__ __align__(16) float As[GT_K][GT_M + 2];
    __shared__ __align__(16) float Bs[GT_K][C1];
    int row0 = blockIdx.x * GT_M;
    int t = threadIdx.x;                  // 256 threads
    int r0 = (t >> 5) * 16;               // 16 rows / warp
    int lane = t & 31;
    int c0 = lane * 4;                    // 4 cols / thread

    // acc2[p][j] = {acc[row 2p][col c0+j], acc[row 2p+1][col c0+j]} f32x2
    uint64_t acc2[8][4];
#pragma unroll
    for (int p = 0; p < 8; p++)
#pragma unroll
        for (int j = 0; j < 4; j++) acc2[p][j] = 0ull;

    for (int k0 = 0; k0 < C1; k0 += GT_K) {
#pragma unroll
        for (int i = 0; i < 16; i++) {         // A tile 128x32
            int idx = t + i * 256;
            int r = idx >> 5, kk = idx & 31;
            int gr = row0 + r;
            As[kk][r] = (gr < N_NODES) ? x[gr * C1 + k0 + kk] : 0.f;
        }
#pragma unroll
        for (int i = 0; i < 16; i++) {         // B tile 32x128
            int idx = t + i * 256;
            int kk = idx >> 7, c = idx & 127;
            Bs[kk][c] = W[(k0 + kk) * C1 + c];
        }
        __syncthreads();
#pragma unroll
        for (int kk = 0; kk < GT_K; kk++) {
            uint64_t ap[8];
#pragma unroll
            for (int p = 0; p < 8; p++)
                ap[p] = *(const uint64_t*)&As[kk][r0 + 2 * p];
            float4 bv = *reinterpret_cast<const float4*>(&Bs[kk][c0]);
            uint64_t bb[4];
            asm("mov.b64 %0, {%1, %1};" : "=l"(bb[0]) : "f"(bv.x));
            asm("mov.b64 %0, {%1, %1};" : "=l"(bb[1]) : "f"(bv.y));
            asm("mov.b64 %0, {%1, %1};" : "=l"(bb[2]) : "f"(bv.z));
            asm("mov.b64 %0, {%1, %1};" : "=l"(bb[3]) : "f"(bv.w));
#pragma unroll
            for (int p = 0; p < 8; p++)
#pragma unroll
                for (int j = 0; j < 4; j++)
                    asm("fma.rn.f32x2 %0, %1, %2, %3;"
                        : "=l"(acc2[p][j])
                        : "l"(ap[p]), "l"(bb[j]), "l"(acc2[p][j]));
        }
        __syncthreads();
    }

    // att vectors for this lane's 4 columns (head = lane>>2, same for all 4)
    float4 as4 = *(const float4*)(att_s + c0);
    float4 ad4 = *(const float4*)(att_d + c0);
    int h = lane >> 2;

#pragma unroll
    for (int p = 0; p < 8; p++) {
        float a0[4], a1[4];
#pragma unroll
        for (int j = 0; j < 4; j++) {
            float lo, hi;
            asm("mov.b64 {%0, %1}, %2;" : "=f"(lo), "=f"(hi) : "l"(acc2[p][j]));
            a0[j] = lo; a1[j] = hi;
        }
#pragma unroll
        for (int q = 0; q < 2; q++) {
            float* ac = q ? a1 : a0;
            int gr = row0 + r0 + 2 * p + q;
            if (gr < N_NODES) {
                __half2 p0 = __floats2half2_rn(ac[0], ac[1]);
                __half2 p1 = __floats2half2_rn(ac[2], ac[3]);
                uint2 pk = make_uint2(*(uint32_t*)&p0, *(uint32_t*)&p1);
                *(uint2*)(g_h1h + (long long)gr * C1 + c0) = pk;
            }
            float ps = ac[0] * as4.x + ac[1] * as4.y + ac[2] * as4.z + ac[3] * as4.w;
            float pd = ac[0] * ad4.x + ac[1] * ad4.y + ac[2] * ad4.z + ac[3] * ad4.w;
            ps += __shfl_xor_sync(0xffffffffu, ps, 1);
            ps += __shfl_xor_sync(0xffffffffu, ps, 2);
            pd += __shfl_xor_sync(0xffffffffu, pd, 1);
            pd += __shfl_xor_sync(0xffffffffu, pd, 2);
            if ((lane & 3) == 0 && gr < N_NODES) {
                g_as1[gr * HEADS + h] = ps;
                g_ad1[gr * HEADS + h] = pd;
            }
        }
    }
}

// ------------- layer-1 aggregation, fused through z (warp per dst node) ----
__global__ void agg1_kernel(const float* __restrict__ b1,
                            const float* __restrict__ W2) {
    int n = blockIdx.x * (blockDim.x >> 5) + (threadIdx.x >> 5);
    if (n >= N_NODES) return;
    int lane = threadIdx.x & 31;
    int h = lane >> 2;                     // head of this lane
    int cnt = g_count[n]; if (cnt > CAP) cnt = CAP;
    float ad = g_ad1[n * HEADS + h];

    float4 acc = make_float4(0.f, 0.f, 0.f, 0.f);
    float wsum = 0.f;
    const int* bucket = g_srcs + n * CAP;

    int i = 0;
    for (; i + 4 <= cnt; i += 4) {
        int s0 = bucket[i], s1 = bucket[i + 1];
        int s2 = bucket[i + 2], s3 = bucket[i + 3];
        float e0 = g_as1[s0 * HEADS + h];
        float e1 = g_as1[s1 * HEADS + h];
        float e2 = g_as1[s2 * HEADS + h];
        float e3 = g_as1[s3 * HEADS + h];
        uint2 r0 = *(const uint2*)(g_h1h + (long long)s0 * C1 + lane * 4);
        uint2 r1 = *(const uint2*)(g_h1h + (long long)s1 * C1 + lane * 4);
        uint2 r2 = *(const uint2*)(g_h1h + (long long)s2 * C1 + lane * 4);
        uint2 r3 = *(const uint2*)(g_h1h + (long long)s3 * C1 + lane * 4);
        float w0 = __expf(lrelu(e0 + ad));
        float w1 = __expf(lrelu(e1 + ad));
        float w2 = __expf(lrelu(e2 + ad));
        float w3 = __expf(lrelu(e3 + ad));
        wsum += (w0 + w1) + (w2 + w3);
        float2 a0 = __half22float2(*(__half2*)&r0.x);
        float2 a1 = __half22float2(*(__half2*)&r0.y);
        float2 b0 = __half22float2(*(__half2*)&r1.x);
        float2 b1v = __half22float2(*(__half2*)&r1.y);
        float2 c0v = __half22float2(*(__half2*)&r2.x);
        float2 c1v = __half22float2(*(__half2*)&r2.y);
        float2 d0 = __half22float2(*(__half2*)&r3.x);
        float2 d1 = __half22float2(*(__half2*)&r3.y);
        acc.x += (w0 * a0.x + w1 * b0.x) + (w2 * c0v.x + w3 * d0.x);
        acc.y += (w0 * a0.y + w1 * b0.y) + (w2 * c0v.y + w3 * d0.y);
        acc.z += (w0 * a1.x + w1 * b1v.x) + (w2 * c1v.x + w3 * d1.x);
        acc.w += (w0 * a1.y + w1 * b1v.y) + (w2 * c1v.y + w3 * d1.y);
    }
    for (; i < cnt; i++) {
        int s0 = bucket[i];
        float e0 = g_as1[s0 * HEADS + h];
        uint2 r0 = *(const uint2*)(g_h1h + (long long)s0 * C1 + lane * 4);
        float2 a0 = __half22float2(*(__half2*)&r0.x);
        float2 a1 = __half22float2(*(__half2*)&r0.y);
        float w0 = __expf(lrelu(e0 + ad));
        wsum += w0;
        acc.x += w0 * a0.x; acc.y += w0 * a0.y;
        acc.z += w0 * a1.x; acc.w += w0 * a1.y;
    }

    float inv = 1.f / (wsum + 1e-16f);
    float4 b = *(const float4*)(b1 + lane * 4);
    float4 w = *(const float4*)(W2 + lane * 4);
    float x0 = acc.x * inv + b.x, x1 = acc.y * inv + b.y;
    float x2 = acc.z * inv + b.z, x3 = acc.w * inv + b.w;
    x0 = x0 > 0.f ? x0 : (__expf(x0) - 1.f);
    x1 = x1 > 0.f ? x1 : (__expf(x1) - 1.f);
    x2 = x2 > 0.f ? x2 : (__expf(x2) - 1.f);
    x3 = x3 > 0.f ? x3 : (__expf(x3) - 1.f);
    float p = x0 * w.x + x1 * w.y + x2 * w.z + x3 * w.w;
#pragma unroll
    for (int o = 16; o; o >>= 1) p += __shfl_xor_sync(0xffffffffu, p, o);
    if (lane == 0) g_z[n] = p;
}

// ------------- layer-2 aggregation (warp per dst node) ---------------------
__global__ void agg2_kernel(const float* __restrict__ att_s,
                            const float* __restrict__ att_d,
                            const float* __restrict__ b2,
                            float* __restrict__ out) {
    int n = blockIdx.x * (blockDim.x >> 5) + (threadIdx.x >> 5);
    if (n >= N_NODES) return;
    int lane = threadIdx.x & 31;
    int cnt = g_count[n]; if (cnt > CAP) cnt = CAP;
    float zd_ad = g_z[n] * att_d[0];
    float a_s = att_s[0];
    const int* bucket = g_srcs + n * CAP;

    float num = 0.f, den = 0.f;
    for (int i = lane; i < cnt; i += 32) {
        int s = bucket[i];
        float zs = g_z[s];
        float w = __expf(lrelu(zs * a_s + zd_ad));
        num += zs * w;
        den += w;
    }
#pragma unroll
    for (int o = 16; o; o >>= 1) {
        num += __shfl_xor_sync(0xffffffffu, num, o);
        den += __shfl_xor_sync(0xffffffffu, den, o);
    }
    if (lane == 0) out[n] = num / (den + 1e-16f) + b2[0];
}

// ------------- launch ------------------------------------------------------
extern "C" void kernel_launch(void* const* d_in, const int* in_sizes, int n_in,
                              void* d_out, int out_size) {
    const float* x        = (const float*)d_in[0];
    const void*  ei       = d_in[1];               // int64 or int32 (detected)
    const float* W1       = (const float*)d_in[2];
    const float* att_src1 = (const float*)d_in[3];
    const float* att_dst1 = (const float*)d_in[4];
    const float* b1       = (const float*)d_in[5];
    const float* W2       = (const float*)d_in[6];
    const float* att_src2 = (const float*)d_in[7];
    const float* att_dst2 = (const float*)d_in[8];
    const float* b2       = (const float*)d_in[9];
    float* out = (float*)d_out;

    // side stream + events (created once on first, uncaptured, call)
    static cudaStream_t s_side = nullptr;
    static cudaEvent_t ev_fork = nullptr, ev_join = nullptr;
    if (!s_side) {
        cudaStreamCreateWithFlags(&s_side, cudaStreamNonBlocking);
        cudaEventCreateWithFlags(&ev_fork, cudaEventDisableTiming);
        cudaEventCreateWithFlags(&ev_join, cudaEventDisableTiming);
    }

    detect_kernel<<<1, 1>>>(ei);

    // fork: zero+scatter on side stream, gemm1 on main stream (disjoint data)
    cudaEventRecord(ev_fork, 0);
    cudaStreamWaitEvent(s_side, ev_fork, 0);

    zero_kernel<<<(N_NODES + 255) / 256, 256, 0, s_side>>>();
    scatter_kernel<<<(E_TOT + 255) / 256, 256, 0, s_side>>>(ei);

    gemm1_kernel<<<(N_NODES + GT_M - 1) / GT_M, 256>>>(x, W1, att_src1, att_dst1);

    // join
    cudaEventRecord(ev_join, s_side);
    cudaStreamWaitEvent(0, ev_join, 0);

    agg1_kernel<<<(N_NODES * 32 + 255) / 256, 256>>>(b1, W2);

    agg2_kernel<<<(N_NODES * 32 + 255) / 256, 256>>>(att_src2, att_dst2, b2, out);
}